// round 1
// baseline (speedup 1.0000x reference)
#include <cuda_runtime.h>
#include <cuda_bf16.h>

#define B_    32
#define T_    512
#define N_    128
#define BN_   4096
#define K_    4
#define PMAX_ 64
#define MINP_ 16
#define CMAX_ 32   // T/MINP

#define GATHERED_ELEMS 33554432ull   // 32*128*4*32*64
#define KAMP_OFFSET    67108864ull   // 2 * GATHERED_ELEMS

// Scratch (device globals: allocation-free per harness rules)
__device__ float g_seqs[BN_ * T_];     // 8 MB, [bn][t]
__device__ int   g_kidx[BN_ * K_];

// ---------------------------------------------------------------------------
// Kernel 1: transpose x[B,T,N] -> g_seqs[(b*N+n)*T + t], fully coalesced
// ---------------------------------------------------------------------------
__global__ void pt_transpose(const float* __restrict__ x) {
    __shared__ float tile[32][33];
    int b  = blockIdx.z;
    int t0 = blockIdx.x * 32;
    int n0 = blockIdx.y * 32;
    int tx = threadIdx.x;       // 0..31
    int ty = threadIdx.y;       // 0..7
#pragma unroll
    for (int i = 0; i < 32; i += 8)
        tile[ty + i][tx] = x[((size_t)b * T_ + (t0 + ty + i)) * N_ + (n0 + tx)];
    __syncthreads();
#pragma unroll
    for (int i = 0; i < 32; i += 8)
        g_seqs[((size_t)(b * N_ + n0 + ty + i)) * T_ + (t0 + tx)] = tile[tx][ty + i];
}

// ---------------------------------------------------------------------------
// Kernel 2: per-sequence 512-pt radix-2 DIT FFT + top-4 amplitudes
// One block (256 threads) per bn. Writes kamp to output, kidx to scratch.
// ---------------------------------------------------------------------------
__global__ __launch_bounds__(256) void pt_fft_topk(float* __restrict__ kamp_out) {
    __shared__ float re[512], im[512];
    __shared__ float wr[256], wi[256];
    __shared__ float amp[256];
    __shared__ float rv[256];
    __shared__ int   ri[256];
    __shared__ int   s_win;
    __shared__ float s_wval;

    const int bn  = blockIdx.x;
    const int tid = threadIdx.x;

    // Twiddles W[j] = exp(-2*pi*i*j/512), computed in double then rounded
    {
        double s, c;
        sincospi(-(double)tid / 256.0, &s, &c);
        wr[tid] = (float)c;
        wi[tid] = (float)s;
    }

    // Load with bit reversal (9-bit)
    for (int t = tid; t < 512; t += 256) {
        int r = __brev((unsigned)t) >> 23;
        re[r] = g_seqs[(size_t)bn * T_ + t];
        im[r] = 0.0f;
    }
    __syncthreads();

    // 9 radix-2 DIT stages; each thread owns one disjoint butterfly per stage
#pragma unroll
    for (int s = 1; s <= 9; s++) {
        int hm  = 1 << (s - 1);
        int k   = tid & (hm - 1);
        int grp = tid >> (s - 1);
        int i1  = (grp << s) + k;
        int i2  = i1 + hm;
        int tw  = k << (9 - s);
        float twr = wr[tw], twi = wi[tw];
        float xr = re[i2], xi = im[i2];
        float tr = twr * xr - twi * xi;
        float ti = twr * xi + twi * xr;
        float ur = re[i1], ui = im[i1];
        re[i1] = ur + tr;  im[i1] = ui + ti;
        re[i2] = ur - tr;  im[i2] = ui - ti;
        __syncthreads();
    }

    // Amplitudes for bins 1..256 (bin 0 is zeroed in reference)
    {
        int f = tid + 1;
        amp[tid] = sqrtf(re[f] * re[f] + im[f] * im[f]);
    }
    __syncthreads();

    // 4 argmax passes; tie-break: equal value -> smaller frequency index
#pragma unroll
    for (int pass = 0; pass < K_; pass++) {
        rv[tid] = amp[tid];
        ri[tid] = tid;
        __syncthreads();
#pragma unroll
        for (int off = 128; off > 0; off >>= 1) {
            if (tid < off) {
                float v2 = rv[tid + off];
                int   j2 = ri[tid + off];
                if (v2 > rv[tid] || (v2 == rv[tid] && j2 < ri[tid])) {
                    rv[tid] = v2;
                    ri[tid] = j2;
                }
            }
            __syncthreads();
        }
        if (tid == 0) { s_win = ri[0]; s_wval = rv[0]; }
        __syncthreads();
        int w = s_win;
        if (tid == 0) {
            g_kidx[bn * K_ + pass]   = w + 1;      // frequency index (>=1)
            kamp_out[bn * K_ + pass] = s_wval;
        }
        if (tid == w) amp[tid] = -1.0f;            // exclude from next pass
        __syncthreads();
    }
}

// ---------------------------------------------------------------------------
// Kernel 3: expansion. One block (256 threads) per (bn,k) pair.
// Writes gathered[bnk][32][64] and mask[bnk][32][64] via float4 streaming stores.
// ---------------------------------------------------------------------------
__global__ __launch_bounds__(256) void pt_gather(float* __restrict__ out) {
    __shared__ float s[512];
    __shared__ int sP, sCyc, sBase;

    const int bnk = blockIdx.x;        // bn*4 + k
    const int tid = threadIdx.x;
    const int bn  = bnk >> 2;

    if (tid == 0) {
        int kidx = g_kidx[bnk];
        int P = T_ / kidx;
        P = (P < MINP_) ? MINP_ : (P > PMAX_ ? PMAX_ : P);
        int cyc = T_ / P;
        sP = P; sCyc = cyc; sBase = T_ - cyc * P;   // >= 0 since cyc*P <= T
    }
    s[tid]       = g_seqs[(size_t)bn * T_ + tid];
    s[tid + 256] = g_seqs[(size_t)bn * T_ + tid + 256];
    __syncthreads();

    const int P = sP, cyc = sCyc, base = sBase;
    float4* gptr = (float4*)(out + (size_t)bnk * (CMAX_ * PMAX_));
    float4* mptr = (float4*)(out + GATHERED_ELEMS + (size_t)bnk * (CMAX_ * PMAX_));

#pragma unroll
    for (int i = 0; i < 2; i++) {
        int e4 = tid + 256 * i;        // float4 index 0..511
        int e  = e4 << 2;              // element index 0..2047
        int c  = e >> 6;               // cycle row
        int p  = e & 63;               // position in period
        int idx = base + c * P + p;
        bool crow = (c < cyc);

        float m0 = (crow && (p     < P)) ? 1.0f : 0.0f;
        float m1 = (crow && (p + 1 < P)) ? 1.0f : 0.0f;
        float m2 = (crow && (p + 2 < P)) ? 1.0f : 0.0f;
        float m3 = (crow && (p + 3 < P)) ? 1.0f : 0.0f;

        // per-lane clip (matches reference's jnp.clip), then mask-multiply
        float v0 = s[min(idx,     T_ - 1)];
        float v1 = s[min(idx + 1, T_ - 1)];
        float v2 = s[min(idx + 2, T_ - 1)];
        float v3 = s[min(idx + 3, T_ - 1)];

        float4 gv = make_float4(m0 * v0, m1 * v1, m2 * v2, m3 * v3);
        float4 mv = make_float4(m0, m1, m2, m3);

        __stcs(gptr + e4, gv);   // streaming: output >> L2, don't pollute
        __stcs(mptr + e4, mv);
    }
}

// ---------------------------------------------------------------------------
extern "C" void kernel_launch(void* const* d_in, const int* in_sizes, int n_in,
                              void* d_out, int out_size) {
    const float* x = (const float*)d_in[0];
    float* out = (float*)d_out;

    dim3 tb(32, 8);
    dim3 tg(T_ / 32, N_ / 32, B_);     // (16, 4, 32)
    pt_transpose<<<tg, tb>>>(x);

    pt_fft_topk<<<BN_, 256>>>(out + KAMP_OFFSET);

    pt_gather<<<BN_ * K_, 256>>>(out);
}

// round 2
// speedup vs baseline: 1.4143x; 1.4143x over previous
#include <cuda_runtime.h>
#include <cuda_bf16.h>

#define B_    32
#define T_    512
#define N_    128
#define BN_   4096
#define K_    4
#define PMAX_ 64
#define MINP_ 16
#define CMAX_ 32   // T/MINP

#define GATHERED_ELEMS 33554432ull   // 32*128*4*32*64
#define KAMP_OFFSET    67108864ull   // 2 * GATHERED_ELEMS

// Twiddles W[j] = exp(-2*pi*i*j/512), j=0..255 (precomputed once, L2-resident)
__device__ float g_twr[256];
__device__ float g_twi[256];

__global__ void pt_twiddle_init() {
    int t = threadIdx.x;
    double s, c;
    sincospi(-(double)t / 256.0, &s, &c);
    g_twr[t] = (float)c;
    g_twi[t] = (float)s;
}

// ---------------------------------------------------------------------------
// Fused kernel: one block (256 threads) per sequence bn = b*N + n.
//  1. strided load of x[b, :, n] (L2-resident: 128 blocks share each line)
//  2. 512-pt radix-2 DIT FFT in shared memory
//  3. top-4 amplitudes via warp-shuffle argmax (jax tie-break: lower index)
//  4. gather + mask expansion, float4 streaming stores
// ---------------------------------------------------------------------------
__global__ __launch_bounds__(256) void pt_fused(const float* __restrict__ x,
                                                float* __restrict__ out) {
    __shared__ float seq[512];
    __shared__ float re[512], im[512];
    __shared__ float wr[256], wi[256];
    __shared__ float swv[8];
    __shared__ int   swj[8];
    __shared__ int   sP[4], sCyc[4], sBase[4];
    __shared__ int   s_win;

    const int bn  = blockIdx.x;
    const int b   = bn >> 7;
    const int n   = bn & 127;
    const int tid = threadIdx.x;
    const int lane = tid & 31;
    const int wid  = tid >> 5;

    wr[tid] = g_twr[tid];
    wi[tid] = g_twi[tid];

    // Load sequence (stride-N gmem reads; x fits in L2) + bit-reversed copy
    {
        float v0 = x[((size_t)b * T_ + tid) * N_ + n];
        float v1 = x[((size_t)b * T_ + tid + 256) * N_ + n];
        seq[tid]       = v0;
        seq[tid + 256] = v1;
        int r0 = __brev((unsigned)tid) >> 23;
        int r1 = __brev((unsigned)(tid + 256)) >> 23;
        re[r0] = v0; im[r0] = 0.0f;
        re[r1] = v1; im[r1] = 0.0f;
    }
    __syncthreads();

    // 9 radix-2 DIT stages; each thread owns one disjoint butterfly per stage
#pragma unroll
    for (int s = 1; s <= 9; s++) {
        int hm  = 1 << (s - 1);
        int k   = tid & (hm - 1);
        int grp = tid >> (s - 1);
        int i1  = (grp << s) + k;
        int i2  = i1 + hm;
        int tw  = k << (9 - s);
        float twr = wr[tw], twi = wi[tw];
        float xr = re[i2], xi = im[i2];
        float tr = twr * xr - twi * xi;
        float ti = twr * xi + twi * xr;
        float ur = re[i1], ui = im[i1];
        re[i1] = ur + tr;  im[i1] = ui + ti;
        re[i2] = ur - tr;  im[i2] = ui - ti;
        __syncthreads();
    }

    // Amplitude of bin tid+1 (bin 0 is zeroed in reference), kept in register
    float v;
    {
        int f = tid + 1;
        float ar = re[f], ai = im[f];
        v = sqrtf(ar * ar + ai * ai);
    }

    // 4 argmax passes via warp shuffles; tie-break: equal value -> lower index
#pragma unroll
    for (int pass = 0; pass < K_; pass++) {
        float bv = v; int bj = tid;
#pragma unroll
        for (int off = 16; off > 0; off >>= 1) {
            float ov = __shfl_down_sync(0xffffffffu, bv, off);
            int   oj = __shfl_down_sync(0xffffffffu, bj, off);
            if (ov > bv || (ov == bv && oj < bj)) { bv = ov; bj = oj; }
        }
        if (lane == 0) { swv[wid] = bv; swj[wid] = bj; }
        __syncthreads();
        if (wid == 0) {
            bv = (lane < 8) ? swv[lane] : -2.0f;
            bj = (lane < 8) ? swj[lane] : 0x7fffffff;
#pragma unroll
            for (int off = 4; off > 0; off >>= 1) {
                float ov = __shfl_down_sync(0xffffffffu, bv, off);
                int   oj = __shfl_down_sync(0xffffffffu, bj, off);
                if (ov > bv || (ov == bv && oj < bj)) { bv = ov; bj = oj; }
            }
            if (lane == 0) {
                s_win = bj;
                out[KAMP_OFFSET + (size_t)bn * K_ + pass] = bv;
                int kidx = bj + 1;                       // frequency index >= 1
                int P = T_ / kidx;
                P = P < MINP_ ? MINP_ : (P > PMAX_ ? PMAX_ : P);
                int cyc = T_ / P;
                sP[pass] = P; sCyc[pass] = cyc; sBase[pass] = T_ - cyc * P;
            }
        }
        __syncthreads();
        if (tid == s_win) v = -1.0f;   // exclude winner from later passes
        // safe: next write to s_win happens only after the next __syncthreads
    }

    // Gather + mask expansion: 4 k-slices of [32 cycles][64 positions]
#pragma unroll
    for (int k = 0; k < K_; k++) {
        const int P = sP[k], cyc = sCyc[k], base = sBase[k];
        float4* gp = (float4*)(out + (size_t)(bn * K_ + k) * (CMAX_ * PMAX_));
        float4* mp = (float4*)(out + GATHERED_ELEMS +
                               (size_t)(bn * K_ + k) * (CMAX_ * PMAX_));
#pragma unroll
        for (int i = 0; i < 2; i++) {
            int e4 = tid + 256 * i;    // float4 index 0..511
            int e  = e4 << 2;          // element index 0..2047
            int c  = e >> 6;           // cycle row
            int p  = e & 63;           // position in period
            int idx = base + c * P + p;
            bool crow = (c < cyc);

            float m0 = (crow && (p     < P)) ? 1.0f : 0.0f;
            float m1 = (crow && (p + 1 < P)) ? 1.0f : 0.0f;
            float m2 = (crow && (p + 2 < P)) ? 1.0f : 0.0f;
            float m3 = (crow && (p + 3 < P)) ? 1.0f : 0.0f;

            // per-lane clip (matches jnp.clip), then mask-multiply
            float v0 = seq[min(idx,     T_ - 1)];
            float v1 = seq[min(idx + 1, T_ - 1)];
            float v2 = seq[min(idx + 2, T_ - 1)];
            float v3 = seq[min(idx + 3, T_ - 1)];

            __stcs(gp + e4, make_float4(m0 * v0, m1 * v1, m2 * v2, m3 * v3));
            __stcs(mp + e4, make_float4(m0, m1, m2, m3));
        }
    }
}

// ---------------------------------------------------------------------------
extern "C" void kernel_launch(void* const* d_in, const int* in_sizes, int n_in,
                              void* d_out, int out_size) {
    const float* x = (const float*)d_in[0];
    float* out = (float*)d_out;

    pt_twiddle_init<<<1, 256>>>();
    pt_fused<<<BN_, 256>>>(x, out);
}

// round 3
// speedup vs baseline: 1.8740x; 1.3251x over previous
#include <cuda_runtime.h>
#include <cuda_bf16.h>

#define B_    32
#define T_    512
#define N_    128
#define BN_   4096
#define K_    4
#define PMAX_ 64
#define MINP_ 16
#define CMAX_ 32   // T/MINP

#define GATHERED_ELEMS 33554432ull   // 32*128*4*32*64
#define KAMP_OFFSET    67108864ull   // 2 * GATHERED_ELEMS

// Twiddles W[j] = exp(-2*pi*i*j/512), j=0..255 (precomputed once, L2-resident)
__device__ float g_twr[256];
__device__ float g_twi[256];

__global__ void pt_twiddle_init() {
    int t = threadIdx.x;
    double s, c;
    sincospi(-(double)t / 256.0, &s, &c);
    g_twr[t] = (float)c;
    g_twi[t] = (float)s;
}

// ---------------------------------------------------------------------------
// Fused kernel: one block (256 threads) per PAIR of sequences (bn0, bn0+1).
//  1. float2 loads of x[b, :, n0:n0+2]  (halves load wavefronts per seq)
//  2. two interleaved 512-pt radix-2 DIT FFTs in shared memory
//  3. top-4 amplitudes: warp 0 handles seq A, warp 1 seq B (jax tie-break)
//  4. gather: warp-per-row, stride-1 conflict-free smem reads, coalesced
//     streaming stores; mask tiles computed without any loads (STG.128)
// ---------------------------------------------------------------------------
__global__ __launch_bounds__(256) void pt_fused(const float* __restrict__ x,
                                                float* __restrict__ out) {
    __shared__ float seqA[512], seqB[512];
    __shared__ float reA[512], imA[512], reB[512], imB[512];
    __shared__ float wr[256], wi[256];
    __shared__ float ampA[256], ampB[256];
    __shared__ int   sP[2][4], sCyc[2][4], sBase[2][4];

    const int bn0 = blockIdx.x * 2;
    const int b   = bn0 >> 7;
    const int n0  = bn0 & 127;            // even
    const int tid = threadIdx.x;
    const int lane = tid & 31;
    const int wid  = tid >> 5;

    wr[tid] = g_twr[tid];
    wi[tid] = g_twi[tid];

    // Load both sequences (float2 across the n-pair) + bit-reversed FFT input
    {
        const float2* xp = (const float2*)(x + (size_t)b * T_ * N_ + n0);
        float2 v0 = xp[(size_t)tid * (N_ / 2)];
        float2 v1 = xp[(size_t)(tid + 256) * (N_ / 2)];
        seqA[tid] = v0.x;        seqB[tid] = v0.y;
        seqA[tid + 256] = v1.x;  seqB[tid + 256] = v1.y;
        int r0 = __brev((unsigned)tid) >> 23;
        int r1 = __brev((unsigned)(tid + 256)) >> 23;
        reA[r0] = v0.x; imA[r0] = 0.0f;  reB[r0] = v0.y; imB[r0] = 0.0f;
        reA[r1] = v1.x; imA[r1] = 0.0f;  reB[r1] = v1.y; imB[r1] = 0.0f;
    }
    __syncthreads();

    // 9 radix-2 DIT stages, two FFTs share index math and barriers
#pragma unroll
    for (int s = 1; s <= 9; s++) {
        int hm  = 1 << (s - 1);
        int k   = tid & (hm - 1);
        int grp = tid >> (s - 1);
        int i1  = (grp << s) + k;
        int i2  = i1 + hm;
        int tw  = k << (9 - s);
        float twr = wr[tw], twi = wi[tw];
        {
            float xr = reA[i2], xi = imA[i2];
            float tr = twr * xr - twi * xi;
            float ti = twr * xi + twi * xr;
            float ur = reA[i1], ui = imA[i1];
            reA[i1] = ur + tr;  imA[i1] = ui + ti;
            reA[i2] = ur - tr;  imA[i2] = ui - ti;
        }
        {
            float xr = reB[i2], xi = imB[i2];
            float tr = twr * xr - twi * xi;
            float ti = twr * xi + twi * xr;
            float ur = reB[i1], ui = imB[i1];
            reB[i1] = ur + tr;  imB[i1] = ui + ti;
            reB[i2] = ur - tr;  imB[i2] = ui - ti;
        }
        __syncthreads();
    }

    // Amplitudes of bins 1..256 (bin 0 zeroed in reference)
    {
        int f = tid + 1;
        float ar = reA[f], ai = imA[f];
        float br = reB[f], bi = imB[f];
        ampA[tid] = sqrtf(ar * ar + ai * ai);
        ampB[tid] = sqrtf(br * br + bi * bi);
    }
    __syncthreads();

    // Warp 0: top-4 of seq A; warp 1: top-4 of seq B.
    // Tie-break everywhere: equal value -> lower frequency index.
    if (wid < 2) {
        float* amp = wid ? ampB : ampA;
        int    bn  = bn0 + wid;
#pragma unroll
        for (int pass = 0; pass < K_; pass++) {
            float bv = -1.0f; int bj = 0;
#pragma unroll
            for (int j = 0; j < 8; j++) {           // ascending: strict > keeps lowest idx
                int   ii = lane + 32 * j;
                float vv = amp[ii];
                if (vv > bv) { bv = vv; bj = ii; }
            }
#pragma unroll
            for (int off = 16; off > 0; off >>= 1) {
                float ov = __shfl_down_sync(0xffffffffu, bv, off);
                int   oj = __shfl_down_sync(0xffffffffu, bj, off);
                if (ov > bv || (ov == bv && oj < bj)) { bv = ov; bj = oj; }
            }
            if (lane == 0) {
                out[KAMP_OFFSET + (size_t)bn * K_ + pass] = bv;
                amp[bj] = -2.0f;                    // exclude from later passes
                int kidx = bj + 1;
                int P = T_ / kidx;
                P = P < MINP_ ? MINP_ : (P > PMAX_ ? PMAX_ : P);
                int cyc = T_ / P;
                sP[wid][pass] = P; sCyc[wid][pass] = cyc;
                sBase[wid][pass] = T_ - cyc * P;
            }
            __syncwarp();
        }
    }
    __syncthreads();

    // Gather + mask expansion for both sequences
#pragma unroll
    for (int sidx = 0; sidx < 2; sidx++) {
        const float* seq = sidx ? seqB : seqA;
        const int bn = bn0 + sidx;
#pragma unroll
        for (int k = 0; k < K_; k++) {
            const int P = sP[sidx][k], cyc = sCyc[sidx][k], base = sBase[sidx][k];
            float* gb = out + (size_t)(bn * K_ + k) * (CMAX_ * PMAX_);
            float* mb = gb + GATHERED_ELEMS;

            // gathered: warp per cycle-row, stride-1 smem reads, coalesced stores
#pragma unroll
            for (int r = 0; r < 4; r++) {
                int c  = wid + 8 * r;
                int rs = base + c * P;
                float mrow = (c < cyc) ? 1.0f : 0.0f;
                float m0 = (lane      < P) ? mrow : 0.0f;
                float m1 = (lane + 32 < P) ? mrow : 0.0f;
                float v0 = m0 * seq[min(rs + lane,      T_ - 1)];
                float v1 = m1 * seq[min(rs + lane + 32, T_ - 1)];
                __stcs(gb + c * PMAX_ + lane,      v0);
                __stcs(gb + c * PMAX_ + lane + 32, v1);
            }

            // mask: no loads, float4 streaming stores
#pragma unroll
            for (int i = 0; i < 2; i++) {
                int e4 = tid + 256 * i;
                int c  = e4 >> 4;
                int p  = (e4 & 15) << 2;
                float mrow = (c < cyc) ? 1.0f : 0.0f;
                float4 mv = make_float4((p     < P) ? mrow : 0.0f,
                                        (p + 1 < P) ? mrow : 0.0f,
                                        (p + 2 < P) ? mrow : 0.0f,
                                        (p + 3 < P) ? mrow : 0.0f);
                __stcs((float4*)mb + e4, mv);
            }
        }
    }
}

// ---------------------------------------------------------------------------
extern "C" void kernel_launch(void* const* d_in, const int* in_sizes, int n_in,
                              void* d_out, int out_size) {
    const float* x = (const float*)d_in[0];
    float* out = (float*)d_out;

    pt_twiddle_init<<<1, 256>>>();
    pt_fused<<<BN_ / 2, 256>>>(x, out);
}